// round 1
// baseline (speedup 1.0000x reference)
#include <cuda_runtime.h>
#include <math.h>
#include <float.h>

// Problem constants
#define BB 4
#define SS 2048
#define EE 1024
#define HH 4
#define DD 256
#define NTOK (BB*SS)  // 8192

// GEMM tiles
#define BM 128
#define BN 128
#define BK 8

// epilogues
#define EPI_NONE      0
#define EPI_SIGMA     1
#define EPI_BIAS      2
#define EPI_MEMREAD_Q 3
#define EPI_MEMREAD_K 4
#define EPI_ACCUM     5
#define EPI_ADDINIT   6

// Scratch (device globals; allocation-free)
__device__ float g_Q  [(size_t)NTOK*EE];
__device__ float g_Kb [(size_t)NTOK*EE];
__device__ float g_V  [(size_t)NTOK*EE];
__device__ float g_SQ [(size_t)NTOK*EE];
__device__ float g_SK [(size_t)NTOK*EE];
__device__ float g_Mrg[(size_t)NTOK*EE];
__device__ float g_U  [(size_t)NTOK*EE];
__device__ float g_W  [(size_t)BB*HH*SS*SS];   // 256 MB score buffer
__device__ float g_Dq [BB*HH*SS];
__device__ float g_Dk [BB*HH*SS];

// ---------------------------------------------------------------------------
// Generic strided-batched SGEMM, 128x128x8 tile, 256 threads, 8x8 micro-tile.
// Batch z -> (b = z/HH, h = z%HH); every operand gets b/h strides.
// TRA: operand is A^T with A stored [K][M]; TRB: operand is B^T with B stored [N][K].
// CSKIP: skip blocks strictly above causal diagonal (for QK^T).
// CLIMK: cap K loop at m0+BM (for P@V under causal mask).
// All M,N multiples of 128 and K multiples of 8 in this problem -> no bounds checks.
// ---------------------------------------------------------------------------
template<int EPI, bool TRA, bool TRB, bool CSKIP, bool CLIMK>
__global__ __launch_bounds__(256) void sgemm(
    const float* __restrict__ A, const float* __restrict__ Bm,
    float* __restrict__ C, float* __restrict__ C2,
    int M, int N, int K, int lda, int ldb, int ldc,
    long long sAb, long long sAh, long long sBb, long long sBh,
    long long sCb, long long sCh,
    const float* __restrict__ aux1, long long s1b, long long s1h,
    const float* __restrict__ aux2, long long s2b, long long s2h,
    const float* __restrict__ betas)
{
    const int zb = blockIdx.z;
    const int b = zb / HH, h = zb % HH;
    A  += b*sAb + h*sAh;
    Bm += b*sBb + h*sBh;
    const long long coff = b*sCb + h*sCh;
    C += coff;
    if (C2)   C2   += coff;
    if (aux1) aux1 += b*s1b + h*s1h;
    if (aux2) aux2 += b*s2b + h*s2h;

    const int m0 = blockIdx.y * BM;
    const int n0 = blockIdx.x * BN;
    if (CSKIP && n0 >= m0 + BM) return;
    const int Keff = CLIMK ? min(K, m0 + BM) : K;

    __shared__ float As[BK][BM];
    __shared__ float Bs[BK][BN];

    const int tid = threadIdx.x;
    const int tx = tid & 15, ty = tid >> 4;

    float acc[8][8];
    #pragma unroll
    for (int i = 0; i < 8; i++)
        #pragma unroll
        for (int j = 0; j < 8; j++) acc[i][j] = 0.f;

    for (int k0 = 0; k0 < Keff; k0 += BK) {
        // ---- load A tile into As[kk][m] ----
        if (!TRA) {
            const int m  = tid >> 1;
            const int kk = (tid & 1) * 4;
            float4 v = *(const float4*)(A + (long long)(m0 + m) * lda + k0 + kk);
            As[kk+0][m] = v.x; As[kk+1][m] = v.y; As[kk+2][m] = v.z; As[kk+3][m] = v.w;
        } else {
            const int kk = tid >> 5;
            const int m  = (tid & 31) * 4;
            float4 v = *(const float4*)(A + (long long)(k0 + kk) * lda + m0 + m);
            *(float4*)&As[kk][m] = v;
        }
        // ---- load B tile into Bs[kk][n] ----
        if (!TRB) {
            const int kk = tid >> 5;
            const int n  = (tid & 31) * 4;
            float4 v = *(const float4*)(Bm + (long long)(k0 + kk) * ldb + n0 + n);
            *(float4*)&Bs[kk][n] = v;
        } else {
            const int n  = tid >> 1;
            const int kk = (tid & 1) * 4;
            float4 v = *(const float4*)(Bm + (long long)(n0 + n) * ldb + k0 + kk);
            Bs[kk+0][n] = v.x; Bs[kk+1][n] = v.y; Bs[kk+2][n] = v.z; Bs[kk+3][n] = v.w;
        }
        __syncthreads();

        #pragma unroll
        for (int kk = 0; kk < BK; kk++) {
            float4 a0 = *(const float4*)&As[kk][ty*4];
            float4 a1 = *(const float4*)&As[kk][64 + ty*4];
            float4 b0 = *(const float4*)&Bs[kk][tx*4];
            float4 b1 = *(const float4*)&Bs[kk][64 + tx*4];
            float ar[8] = {a0.x, a0.y, a0.z, a0.w, a1.x, a1.y, a1.z, a1.w};
            float br[8] = {b0.x, b0.y, b0.z, b0.w, b1.x, b1.y, b1.z, b1.w};
            #pragma unroll
            for (int i = 0; i < 8; i++)
                #pragma unroll
                for (int j = 0; j < 8; j++)
                    acc[i][j] += ar[i] * br[j];
        }
        __syncthreads();
    }

    // ---- epilogue ----
    float gate = 0.f;
    if (EPI == EPI_MEMREAD_Q || EPI == EPI_ACCUM)
        gate = 1.f / (1.f + __expf(-betas[h]));

    #pragma unroll
    for (int i = 0; i < 8; i++) {
        const int r = m0 + ((i < 4) ? (ty*4 + i) : (64 + ty*4 + i - 4));
        float rowscale = 0.f;
        if (EPI == EPI_MEMREAD_Q) rowscale = gate / (aux1[r] + 1e-6f);
        if (EPI == EPI_MEMREAD_K) rowscale = 1.f / (aux1[r] + 1e-6f);
        #pragma unroll
        for (int jq = 0; jq < 2; jq++) {
            const int c = n0 + jq*64 + tx*4;
            const long long idx = (long long)r * ldc + c;
            float4 v = make_float4(acc[i][jq*4+0], acc[i][jq*4+1],
                                   acc[i][jq*4+2], acc[i][jq*4+3]);
            if (EPI == EPI_NONE) {
                *(float4*)(C + idx) = v;
            } else if (EPI == EPI_SIGMA) {
                *(float4*)(C + idx) = v;
                float4 s;
                s.x = v.x > 0.f ? v.x + 1.f : __expf(v.x);
                s.y = v.y > 0.f ? v.y + 1.f : __expf(v.y);
                s.z = v.z > 0.f ? v.z + 1.f : __expf(v.z);
                s.w = v.w > 0.f ? v.w + 1.f : __expf(v.w);
                *(float4*)(C2 + idx) = s;
            } else if (EPI == EPI_BIAS) {
                v.x += aux1[c+0]; v.y += aux1[c+1]; v.z += aux1[c+2]; v.w += aux1[c+3];
                *(float4*)(C + idx) = v;
            } else if (EPI == EPI_MEMREAD_Q) {
                v.x *= rowscale; v.y *= rowscale; v.z *= rowscale; v.w *= rowscale;
                *(float4*)(C + idx) = v;
            } else if (EPI == EPI_MEMREAD_K) {
                float4 vv = *(const float4*)(aux2 + idx);
                v.x = vv.x - v.x * rowscale;
                v.y = vv.y - v.y * rowscale;
                v.z = vv.z - v.z * rowscale;
                v.w = vv.w - v.w * rowscale;
                *(float4*)(C + idx) = v;
            } else if (EPI == EPI_ACCUM) {
                float4 o = *(float4*)(C + idx);
                const float g1 = 1.f - gate;
                o.x += g1 * v.x; o.y += g1 * v.y; o.z += g1 * v.z; o.w += g1 * v.w;
                *(float4*)(C + idx) = o;
            } else if (EPI == EPI_ADDINIT) {
                float4 mi = *(const float4*)(aux1 + idx);
                v.x += mi.x; v.y += mi.y; v.z += mi.z; v.w += mi.w;
                *(float4*)(C + idx) = v;
            }
        }
    }
}

// ---------------------------------------------------------------------------
// Causal row softmax over materialized scores W[(b*H+h)*S*S + q*S + j].
// Valid length per row = q+1; masked tail within the diagonal 128-block is
// zeroed so the causal-capped P@V GEMM reads clean zeros.
// ---------------------------------------------------------------------------
__global__ __launch_bounds__(256) void softmax_kernel(float* __restrict__ W)
{
    const int q = blockIdx.x;
    const int h = blockIdx.y, b = blockIdx.z;
    float* row = W + (((long long)(b*HH + h) * SS + q) * SS);
    const int n = q + 1;
    const int tid = threadIdx.x;
    const int lane = tid & 31, wid = tid >> 5;

    __shared__ float redm[8];
    __shared__ float reds[8];

    float mx = -FLT_MAX;
    for (int j = tid; j < n; j += 256) mx = fmaxf(mx, row[j]);
    #pragma unroll
    for (int o = 16; o; o >>= 1) mx = fmaxf(mx, __shfl_xor_sync(0xffffffffu, mx, o));
    if (lane == 0) redm[wid] = mx;
    __syncthreads();
    mx = fmaxf(fmaxf(fmaxf(redm[0], redm[1]), fmaxf(redm[2], redm[3])),
               fmaxf(fmaxf(redm[4], redm[5]), fmaxf(redm[6], redm[7])));

    float s = 0.f;
    for (int j = tid; j < n; j += 256) {
        float e = __expf(row[j] - mx);
        row[j] = e;
        s += e;
    }
    #pragma unroll
    for (int o = 16; o; o >>= 1) s += __shfl_xor_sync(0xffffffffu, s, o);
    if (lane == 0) reds[wid] = s;
    __syncthreads();
    s = reds[0] + reds[1] + reds[2] + reds[3] + reds[4] + reds[5] + reds[6] + reds[7];
    const float inv = 1.f / s;

    for (int j = tid; j < n; j += 256) row[j] *= inv;
    const int zend = min(SS, ((q >> 7) + 1) << 7);
    for (int j = n + tid; j < zend; j += 256) row[j] = 0.f;
}

// den[b,h,s] = dot(sigma[b,h,s,:], z[h,:])   (one warp per row)
__global__ __launch_bounds__(256) void rowdot_kernel(
    const float* __restrict__ Sig, const float* __restrict__ z, float* __restrict__ Dout)
{
    const int h = blockIdx.y, b = blockIdx.z;
    const int s = blockIdx.x * 8 + (threadIdx.x >> 5);
    const int lane = threadIdx.x & 31;
    const float* p  = Sig + ((long long)(b*SS + s)) * EE + h*DD;
    const float* zp = z + h*DD;
    float acc = 0.f;
    #pragma unroll
    for (int d = lane; d < DD; d += 32) acc += p[d] * zp[d];
    #pragma unroll
    for (int o = 16; o; o >>= 1) acc += __shfl_xor_sync(0xffffffffu, acc, o);
    if (lane == 0) Dout[(b*HH + h) * SS + s] = acc;
}

// z_new[b,h,d] = z[h,d] + sum_s SK[b,h,s,d]
__global__ __launch_bounds__(256) void zupd_kernel(
    const float* __restrict__ SK, const float* __restrict__ z, float* __restrict__ outz)
{
    const int h = blockIdx.x, b = blockIdx.y;
    const int d = threadIdx.x;
    const float* p = SK + ((long long)b * SS) * EE + h*DD + d;
    float acc = 0.f;
    #pragma unroll 8
    for (int s = 0; s < SS; s++) acc += p[(long long)s * EE];
    outz[(b*HH + h) * DD + d] = z[h*DD + d] + acc;
}

// ---------------------------------------------------------------------------
extern "C" void kernel_launch(void* const* d_in, const int* in_sizes, int n_in,
                              void* d_out, int out_size)
{
    const float* X     = (const float*)d_in[0];
    const float* Wq    = (const float*)d_in[1];
    const float* Wk    = (const float*)d_in[2];
    const float* Wv    = (const float*)d_in[3];
    const float* Wo    = (const float*)d_in[4];
    const float* bo    = (const float*)d_in[5];
    const float* betas = (const float*)d_in[6];
    const float* mem   = (const float*)d_in[7];
    const float* z     = (const float*)d_in[8];

    float* out     = (float*)d_out;                       // [B,S,E]
    float* out_mem = out + (size_t)BB*SS*EE;              // [B,H,D,D]
    float* out_z   = out_mem + (size_t)BB*HH*DD*DD;       // [B,H,D,1]

    float *Q, *Kb, *V, *SQ, *SK, *Mrg, *U, *W, *Dq, *Dk;
    cudaGetSymbolAddress((void**)&Q,   g_Q);
    cudaGetSymbolAddress((void**)&Kb,  g_Kb);
    cudaGetSymbolAddress((void**)&V,   g_V);
    cudaGetSymbolAddress((void**)&SQ,  g_SQ);
    cudaGetSymbolAddress((void**)&SK,  g_SK);
    cudaGetSymbolAddress((void**)&Mrg, g_Mrg);
    cudaGetSymbolAddress((void**)&U,   g_U);
    cudaGetSymbolAddress((void**)&W,   g_W);
    cudaGetSymbolAddress((void**)&Dq,  g_Dq);
    cudaGetSymbolAddress((void**)&Dk,  g_Dk);

    const dim3 blk(256);
    typedef long long ll;

    // 1-3) QKV projections (+ ELU+1 sigma for Q,K)
    sgemm<EPI_SIGMA, false, false, false, false><<<dim3(EE/BN, NTOK/BM, 1), blk>>>(
        X, Wq, Q, SQ, NTOK, EE, EE, EE, EE, EE,
        0,0, 0,0, 0,0, nullptr,0,0, nullptr,0,0, nullptr);
    sgemm<EPI_SIGMA, false, false, false, false><<<dim3(EE/BN, NTOK/BM, 1), blk>>>(
        X, Wk, Kb, SK, NTOK, EE, EE, EE, EE, EE,
        0,0, 0,0, 0,0, nullptr,0,0, nullptr,0,0, nullptr);
    sgemm<EPI_NONE, false, false, false, false><<<dim3(EE/BN, NTOK/BM, 1), blk>>>(
        X, Wv, V, nullptr, NTOK, EE, EE, EE, EE, EE,
        0,0, 0,0, 0,0, nullptr,0,0, nullptr,0,0, nullptr);

    // 4) denominators  den = sigma . z
    rowdot_kernel<<<dim3(SS/8, HH, BB), blk>>>(SQ, z, Dq);
    rowdot_kernel<<<dim3(SS/8, HH, BB), blk>>>(SK, z, Dk);

    // 5) Mrg = gate * (SQ @ mem) / (Dq + eps)
    sgemm<EPI_MEMREAD_Q, false, false, false, false><<<dim3(DD/BN, SS/BM, BB*HH), blk>>>(
        SQ, mem, Mrg, nullptr, SS, DD, DD, EE, DD, EE,
        (ll)SS*EE, (ll)DD, 0, (ll)DD*DD, (ll)SS*EE, (ll)DD,
        Dq, (ll)HH*SS, (ll)SS, nullptr,0,0, betas);

    // 6) scores W = Q @ K^T (causal block skip)
    sgemm<EPI_NONE, false, true, true, false><<<dim3(SS/BN, SS/BM, BB*HH), blk>>>(
        Q, Kb, W, nullptr, SS, SS, DD, EE, EE, SS,
        (ll)SS*EE, (ll)DD, (ll)SS*EE, (ll)DD, (ll)HH*SS*SS, (ll)SS*SS,
        nullptr,0,0, nullptr,0,0, nullptr);

    // 7) causal softmax
    softmax_kernel<<<dim3(SS, HH, BB), blk>>>(W);

    // 8) Mrg += (1-gate) * (P @ V)  (K-loop capped at diagonal block)
    sgemm<EPI_ACCUM, false, false, false, true><<<dim3(DD/BN, SS/BM, BB*HH), blk>>>(
        W, V, Mrg, nullptr, SS, DD, SS, SS, EE, EE,
        (ll)HH*SS*SS, (ll)SS*SS, (ll)SS*EE, (ll)DD, (ll)SS*EE, (ll)DD,
        nullptr,0,0, nullptr,0,0, betas);

    // 9) U = V - (SK @ mem) / (Dk + eps)
    sgemm<EPI_MEMREAD_K, false, false, false, false><<<dim3(DD/BN, SS/BM, BB*HH), blk>>>(
        SK, mem, U, nullptr, SS, DD, DD, EE, DD, EE,
        (ll)SS*EE, (ll)DD, 0, (ll)DD*DD, (ll)SS*EE, (ll)DD,
        Dk, (ll)HH*SS, (ll)SS, V, (ll)SS*EE, (ll)DD, nullptr);

    // 10) mem_new = mem + SK^T @ U
    sgemm<EPI_ADDINIT, true, false, false, false><<<dim3(DD/BN, DD/BM, BB*HH), blk>>>(
        SK, U, out_mem, nullptr, DD, DD, SS, EE, EE, DD,
        (ll)SS*EE, (ll)DD, (ll)SS*EE, (ll)DD, (ll)HH*DD*DD, (ll)DD*DD,
        mem, 0, (ll)DD*DD, nullptr,0,0, nullptr);

    // 11) z_new
    zupd_kernel<<<dim3(HH, BB), blk>>>(SK, z, out_z);

    // 12) out = Mrg @ Wo + bo
    sgemm<EPI_BIAS, false, false, false, false><<<dim3(EE/BN, NTOK/BM, 1), blk>>>(
        Mrg, Wo, out, nullptr, NTOK, EE, EE, EE, EE, EE,
        0,0, 0,0, 0,0, bo,0,0, nullptr,0,0, nullptr);
}

// round 5
// speedup vs baseline: 1.2181x; 1.2181x over previous
#include <cuda_runtime.h>
#include <math.h>
#include <float.h>

// Problem constants
#define BB 4
#define SS 2048
#define EE 1024
#define HH 4
#define DD 256
#define NTOK (BB*SS)  // 8192

// GEMM tiles
#define BM 128
#define BN 128
#define BK 16

// epilogues
#define EPI_NONE      0
#define EPI_SIGMA     1
#define EPI_BIAS      2
#define EPI_MEMREAD_Q 3
#define EPI_MEMREAD_K 4
#define EPI_ACCUM     5
#define EPI_ADDINIT   6

typedef unsigned long long u64;

// f32x2 packed helpers (Blackwell FFMA2 path — PTX only, never emitted by ptxas)
__device__ __forceinline__ u64 pk2b(float x) {
    u64 r; asm("mov.b64 %0, {%1, %1};" : "=l"(r) : "f"(x)); return r;
}
__device__ __forceinline__ void fma2(u64& d, u64 a, u64 b) {
    asm("fma.rn.f32x2 %0, %1, %2, %0;" : "+l"(d) : "l"(a), "l"(b));
}
__device__ __forceinline__ float2 upk(u64 v) {
    float2 r; asm("mov.b64 {%0, %1}, %2;" : "=f"(r.x), "=f"(r.y) : "l"(v)); return r;
}

// Scratch (device globals; allocation-free)
__device__ float g_Q  [(size_t)NTOK*EE];
__device__ float g_Kb [(size_t)NTOK*EE];
__device__ float g_V  [(size_t)NTOK*EE];
__device__ float g_SQ [(size_t)NTOK*EE];
__device__ float g_SK [(size_t)NTOK*EE];
__device__ float g_Mrg[(size_t)NTOK*EE];
__device__ float g_U  [(size_t)NTOK*EE];
__device__ float g_W  [(size_t)BB*HH*SS*SS];   // 256 MB score buffer
__device__ float g_Dq [BB*HH*SS];
__device__ float g_Dk [BB*HH*SS];

// ---------------------------------------------------------------------------
// Strided-batched SGEMM, 128x128x16 tile, 256 threads, 8x8 micro-tile with
// packed fma.rn.f32x2 accumulation (2 FLOP-pairs per issue) and double-
// buffered shared memory.
// TRA: operand is A^T with A stored [K][M]; TRB: operand is B^T, B stored [N][K].
// CSKIP: skip blocks strictly above causal diagonal (QK^T).
// CLIMK: cap K loop at m0+BM (P@V under causal mask).
// All M,N multiples of 128, K multiples of 16 here -> no bounds checks.
// ---------------------------------------------------------------------------
template<int EPI, bool TRA, bool TRB, bool CSKIP, bool CLIMK>
__global__ __launch_bounds__(256) void sgemm(
    const float* __restrict__ A, const float* __restrict__ Bm,
    float* __restrict__ C, float* __restrict__ C2,
    int M, int N, int K, int lda, int ldb, int ldc,
    long long sAb, long long sAh, long long sBb, long long sBh,
    long long sCb, long long sCh,
    const float* __restrict__ aux1, long long s1b, long long s1h,
    const float* __restrict__ aux2, long long s2b, long long s2h,
    const float* __restrict__ betas)
{
    const int zb = blockIdx.z;
    const int b = zb / HH, h = zb % HH;
    A  += b*sAb + h*sAh;
    Bm += b*sBb + h*sBh;
    const long long coff = b*sCb + h*sCh;
    C += coff;
    if (C2)   C2   += coff;
    if (aux1) aux1 += b*s1b + h*s1h;
    if (aux2) aux2 += b*s2b + h*s2h;

    const int m0 = blockIdx.y * BM;
    const int n0 = blockIdx.x * BN;
    if (CSKIP && n0 >= m0 + BM) return;
    const int Keff = CLIMK ? min(K, m0 + BM) : K;

    __shared__ float As[2][BK][BM];
    __shared__ float Bs[2][BK][BN];

    const int tid = threadIdx.x;
    const int tx = tid & 15, ty = tid >> 4;

    u64 acc[8][4];
    #pragma unroll
    for (int i = 0; i < 8; i++)
        #pragma unroll
        for (int j = 0; j < 4; j++) acc[i][j] = 0ull;

    float4 pa0, pa1, pb0, pb1;

    // ---- fetch helpers (macros to avoid lambdas) ----
#define FETCH_A(K0) do {                                                        \
        if (!TRA) {                                                             \
            const float* p = A + (long long)(m0 + (tid>>1)) * lda + (K0) + (tid&1)*8; \
            pa0 = *(const float4*)p; pa1 = *(const float4*)(p + 4);             \
        } else {                                                                \
            const float* p = A + (long long)((K0) + (tid>>4)) * lda + m0 + (tid&15)*8; \
            pa0 = *(const float4*)p; pa1 = *(const float4*)(p + 4);             \
        }                                                                       \
    } while (0)

#define FETCH_B(K0) do {                                                        \
        if (!TRB) {                                                             \
            const float* p = Bm + (long long)((K0) + (tid>>4)) * ldb + n0 + (tid&15)*8; \
            pb0 = *(const float4*)p; pb1 = *(const float4*)(p + 4);             \
        } else {                                                                \
            const float* p = Bm + (long long)(n0 + (tid>>1)) * ldb + (K0) + (tid&1)*8; \
            pb0 = *(const float4*)p; pb1 = *(const float4*)(p + 4);             \
        }                                                                       \
    } while (0)

#define STORE_AB(BUF) do {                                                      \
        if (!TRA) {                                                             \
            const int m = tid >> 1, kk = (tid & 1) * 8;                         \
            As[BUF][kk+0][m] = pa0.x; As[BUF][kk+1][m] = pa0.y;                 \
            As[BUF][kk+2][m] = pa0.z; As[BUF][kk+3][m] = pa0.w;                 \
            As[BUF][kk+4][m] = pa1.x; As[BUF][kk+5][m] = pa1.y;                 \
            As[BUF][kk+6][m] = pa1.z; As[BUF][kk+7][m] = pa1.w;                 \
        } else {                                                                \
            const int kk = tid >> 4, m = (tid & 15) * 8;                        \
            *(float4*)&As[BUF][kk][m] = pa0; *(float4*)&As[BUF][kk][m+4] = pa1; \
        }                                                                       \
        if (!TRB) {                                                             \
            const int kk = tid >> 4, n = (tid & 15) * 8;                        \
            *(float4*)&Bs[BUF][kk][n] = pb0; *(float4*)&Bs[BUF][kk][n+4] = pb1; \
        } else {                                                                \
            const int n = tid >> 1, kk = (tid & 1) * 8;                         \
            Bs[BUF][kk+0][n] = pb0.x; Bs[BUF][kk+1][n] = pb0.y;                 \
            Bs[BUF][kk+2][n] = pb0.z; Bs[BUF][kk+3][n] = pb0.w;                 \
            Bs[BUF][kk+4][n] = pb1.x; Bs[BUF][kk+5][n] = pb1.y;                 \
            Bs[BUF][kk+6][n] = pb1.z; Bs[BUF][kk+7][n] = pb1.w;                 \
        }                                                                       \
    } while (0)

    // prologue
    FETCH_A(0); FETCH_B(0);
    STORE_AB(0);
    __syncthreads();

    int buf = 0;
    for (int k0 = 0; k0 < Keff; k0 += BK) {
        const bool more = (k0 + BK) < Keff;
        if (more) { FETCH_A(k0 + BK); FETCH_B(k0 + BK); }

        #pragma unroll
        for (int kk = 0; kk < BK; kk++) {
            float4 a0 = *(const float4*)&As[buf][kk][ty*4];
            float4 a1 = *(const float4*)&As[buf][kk][64 + ty*4];
            ulonglong2 bq0 = *(const ulonglong2*)&Bs[buf][kk][tx*4];
            ulonglong2 bq1 = *(const ulonglong2*)&Bs[buf][kk][64 + tx*4];
            u64 bv0 = bq0.x, bv1 = bq0.y, bv2 = bq1.x, bv3 = bq1.y;
            float ar[8] = {a0.x, a0.y, a0.z, a0.w, a1.x, a1.y, a1.z, a1.w};
            #pragma unroll
            for (int i = 0; i < 8; i++) {
                u64 av = pk2b(ar[i]);
                fma2(acc[i][0], av, bv0);
                fma2(acc[i][1], av, bv1);
                fma2(acc[i][2], av, bv2);
                fma2(acc[i][3], av, bv3);
            }
        }

        if (more) {
            STORE_AB(buf ^ 1);
            __syncthreads();
            buf ^= 1;
        }
    }
#undef FETCH_A
#undef FETCH_B
#undef STORE_AB

    // ---- epilogue ----
    float gate = 0.f;
    if (EPI == EPI_MEMREAD_Q || EPI == EPI_ACCUM)
        gate = 1.f / (1.f + __expf(-betas[h]));

    #pragma unroll
    for (int i = 0; i < 8; i++) {
        const int r = m0 + ((i < 4) ? (ty*4 + i) : (64 + ty*4 + i - 4));
        float rowscale = 0.f;
        if (EPI == EPI_MEMREAD_Q) rowscale = gate / (aux1[r] + 1e-6f);
        if (EPI == EPI_MEMREAD_K) rowscale = 1.f / (aux1[r] + 1e-6f);
        #pragma unroll
        for (int jq = 0; jq < 2; jq++) {
            const int c = n0 + jq*64 + tx*4;
            const long long idx = (long long)r * ldc + c;
            float2 u0 = upk(acc[i][jq*2 + 0]);
            float2 u1 = upk(acc[i][jq*2 + 1]);
            float4 v = make_float4(u0.x, u0.y, u1.x, u1.y);
            if (EPI == EPI_NONE) {
                *(float4*)(C + idx) = v;
            } else if (EPI == EPI_SIGMA) {
                *(float4*)(C + idx) = v;
                float4 s;
                s.x = v.x > 0.f ? v.x + 1.f : __expf(v.x);
                s.y = v.y > 0.f ? v.y + 1.f : __expf(v.y);
                s.z = v.z > 0.f ? v.z + 1.f : __expf(v.z);
                s.w = v.w > 0.f ? v.w + 1.f : __expf(v.w);
                *(float4*)(C2 + idx) = s;
            } else if (EPI == EPI_BIAS) {
                v.x += aux1[c+0]; v.y += aux1[c+1]; v.z += aux1[c+2]; v.w += aux1[c+3];
                *(float4*)(C + idx) = v;
            } else if (EPI == EPI_MEMREAD_Q) {
                v.x *= rowscale; v.y *= rowscale; v.z *= rowscale; v.w *= rowscale;
                *(float4*)(C + idx) = v;
            } else if (EPI == EPI_MEMREAD_K) {
                float4 vv = *(const float4*)(aux2 + idx);
                v.x = vv.x - v.x * rowscale;
                v.y = vv.y - v.y * rowscale;
                v.z = vv.z - v.z * rowscale;
                v.w = vv.w - v.w * rowscale;
                *(float4*)(C + idx) = v;
            } else if (EPI == EPI_ACCUM) {
                float4 o = *(float4*)(C + idx);
                const float g1 = 1.f - gate;
                o.x += g1 * v.x; o.y += g1 * v.y; o.z += g1 * v.z; o.w += g1 * v.w;
                *(float4*)(C + idx) = o;
            } else if (EPI == EPI_ADDINIT) {
                float4 mi = *(const float4*)(aux1 + idx);
                v.x += mi.x; v.y += mi.y; v.z += mi.z; v.w += mi.w;
                *(float4*)(C + idx) = v;
            }
        }
    }
}

// ---------------------------------------------------------------------------
// Causal row softmax over materialized scores W[(b*H+h)*S*S + q*S + j].
// ---------------------------------------------------------------------------
__global__ __launch_bounds__(256) void softmax_kernel(float* __restrict__ W)
{
    const int q = blockIdx.x;
    const int h = blockIdx.y, b = blockIdx.z;
    float* row = W + (((long long)(b*HH + h) * SS + q) * SS);
    const int n = q + 1;
    const int tid = threadIdx.x;
    const int lane = tid & 31, wid = tid >> 5;

    __shared__ float redm[8];
    __shared__ float reds[8];

    float mx = -FLT_MAX;
    for (int j = tid; j < n; j += 256) mx = fmaxf(mx, row[j]);
    #pragma unroll
    for (int o = 16; o; o >>= 1) mx = fmaxf(mx, __shfl_xor_sync(0xffffffffu, mx, o));
    if (lane == 0) redm[wid] = mx;
    __syncthreads();
    mx = fmaxf(fmaxf(fmaxf(redm[0], redm[1]), fmaxf(redm[2], redm[3])),
               fmaxf(fmaxf(redm[4], redm[5]), fmaxf(redm[6], redm[7])));

    float s = 0.f;
    for (int j = tid; j < n; j += 256) {
        float e = __expf(row[j] - mx);
        row[j] = e;
        s += e;
    }
    #pragma unroll
    for (int o = 16; o; o >>= 1) s += __shfl_xor_sync(0xffffffffu, s, o);
    if (lane == 0) reds[wid] = s;
    __syncthreads();
    s = reds[0] + reds[1] + reds[2] + reds[3] + reds[4] + reds[5] + reds[6] + reds[7];
    const float inv = 1.f / s;

    for (int j = tid; j < n; j += 256) row[j] *= inv;
    const int zend = min(SS, ((q >> 7) + 1) << 7);
    for (int j = n + tid; j < zend; j += 256) row[j] = 0.f;
}

// den[b,h,s] = dot(sigma[b,h,s,:], z[h,:])   (one warp per row)
__global__ __launch_bounds__(256) void rowdot_kernel(
    const float* __restrict__ Sig, const float* __restrict__ z, float* __restrict__ Dout)
{
    const int h = blockIdx.y, b = blockIdx.z;
    const int s = blockIdx.x * 8 + (threadIdx.x >> 5);
    const int lane = threadIdx.x & 31;
    const float* p  = Sig + ((long long)(b*SS + s)) * EE + h*DD;
    const float* zp = z + h*DD;
    float acc = 0.f;
    #pragma unroll
    for (int d = lane; d < DD; d += 32) acc += p[d] * zp[d];
    #pragma unroll
    for (int o = 16; o; o >>= 1) acc += __shfl_xor_sync(0xffffffffu, acc, o);
    if (lane == 0) Dout[(b*HH + h) * SS + s] = acc;
}

// z_new[b,h,d] = z[h,d] + sum_s SK[b,h,s,d]
__global__ __launch_bounds__(256) void zupd_kernel(
    const float* __restrict__ SK, const float* __restrict__ z, float* __restrict__ outz)
{
    const int h = blockIdx.x, b = blockIdx.y;
    const int d = threadIdx.x;
    const float* p = SK + ((long long)b * SS) * EE + h*DD + d;
    float acc = 0.f;
    #pragma unroll 8
    for (int s = 0; s < SS; s++) acc += p[(long long)s * EE];
    outz[(b*HH + h) * DD + d] = z[h*DD + d] + acc;
}

// ---------------------------------------------------------------------------
extern "C" void kernel_launch(void* const* d_in, const int* in_sizes, int n_in,
                              void* d_out, int out_size)
{
    const float* X     = (const float*)d_in[0];
    const float* Wq    = (const float*)d_in[1];
    const float* Wk    = (const float*)d_in[2];
    const float* Wv    = (const float*)d_in[3];
    const float* Wo    = (const float*)d_in[4];
    const float* bo    = (const float*)d_in[5];
    const float* betas = (const float*)d_in[6];
    const float* mem   = (const float*)d_in[7];
    const float* z     = (const float*)d_in[8];

    float* out     = (float*)d_out;                       // [B,S,E]
    float* out_mem = out + (size_t)BB*SS*EE;              // [B,H,D,D]
    float* out_z   = out_mem + (size_t)BB*HH*DD*DD;       // [B,H,D,1]

    float *Q, *Kb, *V, *SQ, *SK, *Mrg, *U, *W, *Dq, *Dk;
    cudaGetSymbolAddress((void**)&Q,   g_Q);
    cudaGetSymbolAddress((void**)&Kb,  g_Kb);
    cudaGetSymbolAddress((void**)&V,   g_V);
    cudaGetSymbolAddress((void**)&SQ,  g_SQ);
    cudaGetSymbolAddress((void**)&SK,  g_SK);
    cudaGetSymbolAddress((void**)&Mrg, g_Mrg);
    cudaGetSymbolAddress((void**)&U,   g_U);
    cudaGetSymbolAddress((void**)&W,   g_W);
    cudaGetSymbolAddress((void**)&Dq,  g_Dq);
    cudaGetSymbolAddress((void**)&Dk,  g_Dk);

    const dim3 blk(256);
    typedef long long ll;

    // 1-3) QKV projections (+ ELU+1 sigma for Q,K)
    sgemm<EPI_SIGMA, false, false, false, false><<<dim3(EE/BN, NTOK/BM, 1), blk>>>(
        X, Wq, Q, SQ, NTOK, EE, EE, EE, EE, EE,
        0,0, 0,0, 0,0, nullptr,0,0, nullptr,0,0, nullptr);
    sgemm<EPI_SIGMA, false, false, false, false><<<dim3(EE/BN, NTOK/BM, 1), blk>>>(
        X, Wk, Kb, SK, NTOK, EE, EE, EE, EE, EE,
        0,0, 0,0, 0,0, nullptr,0,0, nullptr,0,0, nullptr);
    sgemm<EPI_NONE, false, false, false, false><<<dim3(EE/BN, NTOK/BM, 1), blk>>>(
        X, Wv, V, nullptr, NTOK, EE, EE, EE, EE, EE,
        0,0, 0,0, 0,0, nullptr,0,0, nullptr,0,0, nullptr);

    // 4) denominators  den = sigma . z
    rowdot_kernel<<<dim3(SS/8, HH, BB), blk>>>(SQ, z, Dq);
    rowdot_kernel<<<dim3(SS/8, HH, BB), blk>>>(SK, z, Dk);

    // 5) Mrg = gate * (SQ @ mem) / (Dq + eps)
    sgemm<EPI_MEMREAD_Q, false, false, false, false><<<dim3(DD/BN, SS/BM, BB*HH), blk>>>(
        SQ, mem, Mrg, nullptr, SS, DD, DD, EE, DD, EE,
        (ll)SS*EE, (ll)DD, 0, (ll)DD*DD, (ll)SS*EE, (ll)DD,
        Dq, (ll)HH*SS, (ll)SS, nullptr,0,0, betas);

    // 6) scores W = Q @ K^T (causal block skip)
    sgemm<EPI_NONE, false, true, true, false><<<dim3(SS/BN, SS/BM, BB*HH), blk>>>(
        Q, Kb, W, nullptr, SS, SS, DD, EE, EE, SS,
        (ll)SS*EE, (ll)DD, (ll)SS*EE, (ll)DD, (ll)HH*SS*SS, (ll)SS*SS,
        nullptr,0,0, nullptr,0,0, nullptr);

    // 7) causal softmax
    softmax_kernel<<<dim3(SS, HH, BB), blk>>>(W);

    // 8) Mrg += (1-gate) * (P @ V)  (K-loop capped at diagonal block)
    sgemm<EPI_ACCUM, false, false, false, true><<<dim3(DD/BN, SS/BM, BB*HH), blk>>>(
        W, V, Mrg, nullptr, SS, DD, SS, SS, EE, EE,
        (ll)HH*SS*SS, (ll)SS*SS, (ll)SS*EE, (ll)DD, (ll)SS*EE, (ll)DD,
        nullptr,0,0, nullptr,0,0, betas);

    // 9) U = V - (SK @ mem) / (Dk + eps)
    sgemm<EPI_MEMREAD_K, false, false, false, false><<<dim3(DD/BN, SS/BM, BB*HH), blk>>>(
        SK, mem, U, nullptr, SS, DD, DD, EE, DD, EE,
        (ll)SS*EE, (ll)DD, 0, (ll)DD*DD, (ll)SS*EE, (ll)DD,
        Dk, (ll)HH*SS, (ll)SS, V, (ll)SS*EE, (ll)DD, nullptr);

    // 10) mem_new = mem + SK^T @ U
    sgemm<EPI_ADDINIT, true, false, false, false><<<dim3(DD/BN, DD/BM, BB*HH), blk>>>(
        SK, U, out_mem, nullptr, DD, DD, SS, EE, EE, DD,
        (ll)SS*EE, (ll)DD, (ll)SS*EE, (ll)DD, (ll)HH*DD*DD, (ll)DD*DD,
        mem, 0, (ll)DD*DD, nullptr,0,0, nullptr);

    // 11) z_new
    zupd_kernel<<<dim3(HH, BB), blk>>>(SK, z, out_z);

    // 12) out = Mrg @ Wo + bo
    sgemm<EPI_BIAS, false, false, false, false><<<dim3(EE/BN, NTOK/BM, 1), blk>>>(
        Mrg, Wo, out, nullptr, NTOK, EE, EE, EE, EE, EE,
        0,0, 0,0, 0,0, bo,0,0, nullptr,0,0, nullptr);
}